// round 7
// baseline (speedup 1.0000x reference)
#include <cuda_runtime.h>
#include <cstdint>

// ===========================================================================
// OctreeGnResBlock2 via mma.sync tf32 + deep cp.async pipelines (hoisted
// addressing, smem index table).
//   kA : h  = relu(GN_a(sum_k gather(x) @ Wa[k]))          27 K=32 taps, d3
//   kB : out= relu(GN_b(sum_k gather(h) @ Wb[k]) + GN_s(x @ W1))
//        54 K=32 half-taps + shortcut stage, depth-4 (wait_group 2)
// CTA = 128 nodes / 256 thr; 8 warps tile 128x64 as 4(m32) x 2(n32).
// Stage = A 16KB + W 8KB, XOR-swizzled 16B blocks (conflict-free).
// ===========================================================================

__device__ float g_h  [800000ULL * 64];  // tf32-rounded activations
__device__ float g_xt [800000ULL * 32];  // tf32-rounded input
__device__ float g_Wat[27 * 64 * 32];    // [k][cout][cin] tf32
__device__ float g_Wbt[27 * 64 * 64];
__device__ float g_W1t[64 * 32];

__device__ __forceinline__ float totf32(float f) {
    uint32_t u;
    asm("cvt.rna.tf32.f32 %0, %1;" : "=r"(u) : "f"(f));
    return __uint_as_float(u);
}
__device__ __forceinline__ uint32_t s2u(const void* p) {
    uint32_t a;
    asm("{ .reg .u64 t; cvta.to.shared.u64 t, %1; cvt.u32.u64 %0, t; }"
        : "=r"(a) : "l"(p));
    return a;
}
__device__ __forceinline__ void cpa16(uint32_t d, const void* s) {
    asm volatile("cp.async.cg.shared.global [%0], [%1], 16;" :: "r"(d), "l"(s));
}
#define CPA_COMMIT() asm volatile("cp.async.commit_group;" ::: "memory")
#define CPA_WAIT(N)  asm volatile("cp.async.wait_group %0;" :: "n"(N) : "memory")

#define MMA(c, a, b0, b1)                                                    \
    asm volatile(                                                            \
        "mma.sync.aligned.m16n8k8.row.col.f32.tf32.tf32.f32 "                \
        "{%0,%1,%2,%3},{%4,%5,%6,%7},{%8,%9},{%0,%1,%2,%3};"                 \
        : "+f"((c)[0]), "+f"((c)[1]), "+f"((c)[2]), "+f"((c)[3])             \
        : "r"((a)[0]), "r"((a)[1]), "r"((a)[2]), "r"((a)[3]),                \
          "r"(b0), "r"(b1))

// one K=32 stage: A[128x32] @ B[64x32]^T into c[2][4][4]; 8-block swizzle
__device__ __forceinline__ void tap_mma32(const float* __restrict__ sA,
                                          const float* __restrict__ sW,
                                          float c[2][4][4], int lid, int wid) {
    const int g = lid >> 2, t = lid & 3;
    const float* pa = sA + ((wid & 3) * 32 + g) * 32 + t;
    const float* pb = sW + ((wid >> 2) * 32 + g) * 32 + t;
#pragma unroll
    for (int s = 0; s < 4; ++s) {
        const int o0 = (((2 * s) & 7) ^ g) * 4;
        const int o1 = (((2 * s + 1) & 7) ^ g) * 4;
        uint32_t a[2][4];
#pragma unroll
        for (int m = 0; m < 2; ++m) {
            const float* p = pa + m * 16 * 32;
            a[m][0] = __float_as_uint(p[o0]);
            a[m][1] = __float_as_uint(p[8 * 32 + o0]);
            a[m][2] = __float_as_uint(p[o1]);
            a[m][3] = __float_as_uint(p[8 * 32 + o1]);
        }
#pragma unroll
        for (int nn = 0; nn < 4; ++nn) {
            const float* q = pb + nn * 8 * 32;
            const uint32_t b0 = __float_as_uint(q[o0]);
            const uint32_t b1 = __float_as_uint(q[o1]);
            MMA(c[0][nn], a[0], b0, b1);
            MMA(c[1][nn], a[1], b0, b1);
        }
    }
}

// ---------------- prep ----------------
__global__ void k_prepW(const float* __restrict__ Wa,
                        const float* __restrict__ Wb,
                        const float* __restrict__ W1) {
    const int t = blockIdx.x * 256 + threadIdx.x;
    if (t < 27 * 64 * 32) {
        const int k = t / 2048, o = (t % 2048) / 32, i = t % 32;
        g_Wat[t] = totf32(Wa[k * 2048 + i * 64 + o]);
    }
    if (t < 27 * 64 * 64) {
        const int k = t / 4096, o = (t % 4096) / 64, i = t % 64;
        g_Wbt[t] = totf32(Wb[k * 4096 + i * 64 + o]);
    }
    if (t < 2048) {
        const int o = t / 32, i = t % 32;
        g_W1t[t] = totf32(W1[i * 64 + o]);
    }
}
__global__ void k_prepX(const float* __restrict__ x, long long n32) {
    for (long long i = blockIdx.x * 256LL + threadIdx.x; i < n32;
         i += (long long)gridDim.x * 256)
        g_xt[i] = totf32(x[i]);
}

static constexpr int STG = 24576;      // A 16KB + W 8KB per stage
static constexpr int NEI = 13824;      // 128*27 ints

// ---------------- kernel A: 27 K=32 taps, depth 3 ----------------
static constexpr int A_SM = NEI + 3 * STG;     // 87552

__global__ void __launch_bounds__(256, 2) kA(
    const int* __restrict__ neigh, const float* __restrict__ gw,
    const float* __restrict__ gb, int n)
{
    extern __shared__ char smem[];
    int* snei = (int*)smem;
    const uint32_t sbase = s2u(smem) + NEI;
    const int tid = threadIdx.x, wid = tid >> 5, lid = tid & 31;
    const int tile = blockIdx.x;
    const int rows = min(128, n - tile * 128);

    for (int i = tid; i < rows * 27; i += 256)
        snei[i] = neigh[(long long)tile * 128 * 27 + i];
    __syncthreads();

    // hoisted staging constants
    const int seg = tid & 7, r0 = tid >> 3;        // seg 0..7, r0 0..31
    const int sw = (seg ^ (r0 & 7)) * 16 + seg * 0;
    uint32_t dA[4], dW[2];
    const int* nptr[4];
#pragma unroll
    for (int q = 0; q < 4; ++q) {
        const int row = r0 + q * 32;
        dA[q] = sbase + row * 128 + sw;            // row*8 blocks *16B
        nptr[q] = snei + row * 27;
    }
#pragma unroll
    for (int q = 0; q < 2; ++q)
        dW[q] = sbase + 16384 + (r0 + q * 32) * 128 + sw;
    const float* wsrc0 = g_Wat + (long long)(r0) * 32 + seg * 4;
    const float* wsrc1 = g_Wat + (long long)(r0 + 32) * 32 + seg * 4;
    const long long segoff = seg * 4;

    float c[2][4][4];
#pragma unroll
    for (int m = 0; m < 2; ++m)
#pragma unroll
        for (int nn = 0; nn < 4; ++nn)
#pragma unroll
            for (int j = 0; j < 4; ++j) c[m][nn][j] = 0.f;

    auto stage = [&](int k) {
        const uint32_t so = (uint32_t)(k % 3) * STG;
#pragma unroll
        for (int q = 0; q < 4; ++q) {
            const long long idx = nptr[q][k];
            cpa16(dA[q] + so, g_xt + idx * 32 + segoff);
        }
        cpa16(dW[0] + so, wsrc0 + k * 2048);
        cpa16(dW[1] + so, wsrc1 + k * 2048);
        CPA_COMMIT();
    };

    stage(0); stage(1);
    for (int k = 0; k < 27; ++k) {
        CPA_WAIT(1);
        __syncthreads();
        if (k + 2 < 27) stage(k + 2); else CPA_COMMIT();
        const float* aF = (const float*)(smem + NEI + (k % 3) * STG);
        tap_mma32(aF, aF + 4096, c, lid, wid);
    }

    const int g = lid >> 2, t = lid & 3;
    const int mbase = (wid & 3) * 32, nbase = (wid >> 2) * 32;
#pragma unroll
    for (int m = 0; m < 2; ++m)
#pragma unroll
        for (int h = 0; h < 2; ++h) {
            const int row = mbase + m * 16 + g + h * 8;
#pragma unroll
            for (int nn = 0; nn < 4; ++nn) {
                const float v0 = c[m][nn][h * 2], v1 = c[m][nn][h * 2 + 1];
                float s = v0 + v1;
                s += __shfl_xor_sync(0xffffffffu, s, 1);
                const float mu = s * 0.25f;
                const float d0 = v0 - mu, d1 = v1 - mu;
                float q = d0 * d0 + d1 * d1;
                q += __shfl_xor_sync(0xffffffffu, q, 1);
                const float rs = rsqrtf(q * 0.25f + 1e-5f);
                const int col = nbase + nn * 8 + t * 2;
                if (row < rows) {
                    float2 o;
                    o.x = totf32(fmaxf(fmaf(d0 * rs, __ldg(gw + col),
                                            __ldg(gb + col)), 0.f));
                    o.y = totf32(fmaxf(fmaf(d1 * rs, __ldg(gw + col + 1),
                                            __ldg(gb + col + 1)), 0.f));
                    *(float2*)(g_h + ((long long)tile * 128 + row) * 64 + col) = o;
                }
            }
        }
}

// ---------------- kernel B: 54 half-taps + shortcut, depth 4 ----------------
static constexpr int B_SM = NEI + 4 * STG;     // 112128

__global__ void __launch_bounds__(256, 2) kB(
    const int* __restrict__ neigh,
    const float* __restrict__ gbw, const float* __restrict__ gbb,
    const float* __restrict__ gsw, const float* __restrict__ gsb,
    float* __restrict__ out, int n)
{
    extern __shared__ char smem[];
    int* snei = (int*)smem;
    const uint32_t sbase = s2u(smem) + NEI;
    const int tid = threadIdx.x, wid = tid >> 5, lid = tid & 31;
    const int tile = blockIdx.x;
    const int rows = min(128, n - tile * 128);

    for (int i = tid; i < rows * 27; i += 256)
        snei[i] = neigh[(long long)tile * 128 * 27 + i];
    __syncthreads();

    const int seg = tid & 7, r0 = tid >> 3;
    const int sw = (seg ^ (r0 & 7)) * 16;
    uint32_t dA[4], dW[2];
    const int* nptr[4];
    const float* xsrc[4];
#pragma unroll
    for (int q = 0; q < 4; ++q) {
        const int row = r0 + q * 32;
        dA[q] = sbase + row * 128 + sw;
        nptr[q] = snei + row * 27;
        const long long nd = (long long)tile * 128 + ((row < rows) ? row : 0);
        xsrc[q] = g_xt + nd * 32 + seg * 4;
    }
#pragma unroll
    for (int q = 0; q < 2; ++q)
        dW[q] = sbase + 16384 + (r0 + q * 32) * 128 + sw;
    const float* wsrc0 = g_Wbt + (long long)(r0) * 64 + seg * 4;
    const float* wsrc1 = g_Wbt + (long long)(r0 + 32) * 64 + seg * 4;
    const float* w1src0 = g_W1t + (long long)(r0) * 32 + seg * 4;
    const float* w1src1 = g_W1t + (long long)(r0 + 32) * 32 + seg * 4;
    const long long segoff = seg * 4;

    float c[2][4][4], csc[2][4][4];
#pragma unroll
    for (int m = 0; m < 2; ++m)
#pragma unroll
        for (int nn = 0; nn < 4; ++nn)
#pragma unroll
            for (int j = 0; j < 4; ++j) { c[m][nn][j] = 0.f; csc[m][nn][j] = 0.f; }

    auto stage = [&](int s) {
        const uint32_t so = (uint32_t)(s & 3) * STG;
        if (s < 54) {
            const int k = s >> 1, hf = (s & 1) * 32;
#pragma unroll
            for (int q = 0; q < 4; ++q) {
                const long long idx = nptr[q][k];
                cpa16(dA[q] + so, g_h + idx * 64 + hf + segoff);
            }
            cpa16(dW[0] + so, wsrc0 + k * 4096 + hf);
            cpa16(dW[1] + so, wsrc1 + k * 4096 + hf);
        } else {                                   // shortcut: x @ W1t
#pragma unroll
            for (int q = 0; q < 4; ++q) cpa16(dA[q] + so, xsrc[q]);
            cpa16(dW[0] + so, w1src0);
            cpa16(dW[1] + so, w1src1);
        }
        CPA_COMMIT();
    };

    stage(0); stage(1); stage(2);
    for (int s = 0; s < 55; ++s) {
        CPA_WAIT(2);
        __syncthreads();
        if (s + 3 < 55) stage(s + 3); else CPA_COMMIT();
        const float* aF = (const float*)(smem + NEI + (s & 3) * STG);
        tap_mma32(aF, aF + 4096, (s < 54) ? c : csc, lid, wid);
    }

    const int g = lid >> 2, t = lid & 3;
    const int mbase = (wid & 3) * 32, nbase = (wid >> 2) * 32;
#pragma unroll
    for (int m = 0; m < 2; ++m)
#pragma unroll
        for (int h = 0; h < 2; ++h) {
            const int row = mbase + m * 16 + g + h * 8;
#pragma unroll
            for (int nn = 0; nn < 4; ++nn) {
                const float v0 = c[m][nn][h * 2], v1 = c[m][nn][h * 2 + 1];
                float s = v0 + v1;
                s += __shfl_xor_sync(0xffffffffu, s, 1);
                const float mub = s * 0.25f;
                const float d0 = v0 - mub, d1 = v1 - mub;
                float q = d0 * d0 + d1 * d1;
                q += __shfl_xor_sync(0xffffffffu, q, 1);
                const float rb = rsqrtf(q * 0.25f + 1e-5f);

                const float w0 = csc[m][nn][h * 2], w1 = csc[m][nn][h * 2 + 1];
                float s2 = w0 + w1;
                s2 += __shfl_xor_sync(0xffffffffu, s2, 1);
                const float mus = s2 * 0.25f;
                const float e0 = w0 - mus, e1 = w1 - mus;
                float q2 = e0 * e0 + e1 * e1;
                q2 += __shfl_xor_sync(0xffffffffu, q2, 1);
                const float rss = rsqrtf(q2 * 0.25f + 1e-5f);

                const int col = nbase + nn * 8 + t * 2;
                if (row < rows) {
                    float2 o;
                    o.x = fmaxf(fmaf(d0 * rb, __ldg(gbw + col), __ldg(gbb + col)) +
                                fmaf(e0 * rss, __ldg(gsw + col), __ldg(gsb + col)),
                                0.f);
                    o.y = fmaxf(fmaf(d1 * rb, __ldg(gbw + col + 1), __ldg(gbb + col + 1)) +
                                fmaf(e1 * rss, __ldg(gsw + col + 1), __ldg(gsb + col + 1)),
                                0.f);
                    *(float2*)(out + ((long long)tile * 128 + row) * 64 + col) = o;
                }
            }
        }
}

// ---------------------------------------------------------------------------
extern "C" void kernel_launch(void* const* d_in, const int* in_sizes, int n_in,
                              void* d_out, int out_size) {
    const float* data  = (const float*)d_in[0];
    const int*   neigh = (const int*)d_in[1];
    const float* Wa    = (const float*)d_in[2];
    const float* ga_w  = (const float*)d_in[3];
    const float* ga_b  = (const float*)d_in[4];
    const float* Wb    = (const float*)d_in[5];
    const float* gb_w  = (const float*)d_in[6];
    const float* gb_b  = (const float*)d_in[7];
    const float* W1    = (const float*)d_in[8];
    const float* gs_w  = (const float*)d_in[9];
    const float* gs_b  = (const float*)d_in[10];
    float* out = (float*)d_out;

    const int n = in_sizes[0] / 32;
    const int tiles = (n + 127) / 128;

    cudaFuncSetAttribute(kA, cudaFuncAttributeMaxDynamicSharedMemorySize, A_SM);
    cudaFuncSetAttribute(kB, cudaFuncAttributeMaxDynamicSharedMemorySize, B_SM);

    k_prepW<<<(27 * 64 * 64 + 255) / 256, 256>>>(Wa, Wb, W1);
    k_prepX<<<2048, 256>>>(data, (long long)n * 32);
    kA<<<tiles, 256, A_SM>>>(neigh, ga_w, ga_b, n);
    kB<<<tiles, 256, B_SM>>>(neigh, gb_w, gb_b, gs_w, gs_b, out, n);
}

// round 8
// speedup vs baseline: 1.9959x; 1.9959x over previous
#include <cuda_runtime.h>
#include <cstdint>

// ===========================================================================
// OctreeGnResBlock2: mma.sync tf32, ldmatrix fragments, 256-node tiles.
//   kS : g_sc = GN_s(x @ W1)                     (1 MMA stage)
//   kA : g_h  = relu(GN_a(sum_k gather(x) @ Wa[k])) tf32   27 K=32 stages
//   kB : out  = relu(GN_b(sum_k gather(h) @ Wb[k]) + g_sc) 54 K=32 stages
// CTA = 256 nodes / 256 thr; 8 warps = 4(m64) x 2(n32).
// Stage = A 32KB (256x32f) + W 8KB (64x32f), 16B-chunk XOR swizzle,
// double-buffered cp.async; fragments via ldmatrix.m8n8.x4.b16.
// ===========================================================================

__device__ float g_h  [800000ULL * 64];
__device__ float g_sc [800000ULL * 64];
__device__ float g_xt [800000ULL * 32];
__device__ float g_Wat[27 * 64 * 32];
__device__ float g_Wbt[27 * 64 * 64];
__device__ float g_W1t[64 * 32];

__device__ __forceinline__ float totf32(float f) {
    uint32_t u;
    asm("cvt.rna.tf32.f32 %0, %1;" : "=r"(u) : "f"(f));
    return __uint_as_float(u);
}
__device__ __forceinline__ uint32_t s2u(const void* p) {
    uint32_t a;
    asm("{ .reg .u64 t; cvta.to.shared.u64 t, %1; cvt.u32.u64 %0, t; }"
        : "=r"(a) : "l"(p));
    return a;
}
__device__ __forceinline__ void cpa16(uint32_t d, const void* s) {
    asm volatile("cp.async.cg.shared.global [%0], [%1], 16;" :: "r"(d), "l"(s));
}
#define CPA_COMMIT() asm volatile("cp.async.commit_group;" ::: "memory")
#define CPA_WAIT0()  asm volatile("cp.async.wait_group 0;"  ::: "memory")

#define LDSM4(d0, d1, d2, d3, addr)                                          \
    asm volatile("ldmatrix.sync.aligned.m8n8.x4.shared.b16 {%0,%1,%2,%3}, [%4];" \
                 : "=r"(d0), "=r"(d1), "=r"(d2), "=r"(d3) : "r"(addr))

#define MMA(c, a, b0, b1)                                                    \
    asm volatile(                                                            \
        "mma.sync.aligned.m16n8k8.row.col.f32.tf32.tf32.f32 "                \
        "{%0,%1,%2,%3},{%4,%5,%6,%7},{%8,%9},{%0,%1,%2,%3};"                 \
        : "+f"((c)[0]), "+f"((c)[1]), "+f"((c)[2]), "+f"((c)[3])             \
        : "r"((a)[0]), "r"((a)[1]), "r"((a)[2]), "r"((a)[3]),                \
          "r"(b0), "r"(b1))

// --- one K=32 stage: A[256x32] @ W[64x32]^T, warp tile m64n32 ---
// pA/pB/rxA/rxB are lane-constant (hoisted by caller).
__device__ __forceinline__ void mma_stage(uint32_t aSt, float c[4][4][4],
                                          uint32_t pA, uint32_t pB,
                                          uint32_t rxA, uint32_t rxB) {
    const uint32_t wSt = aSt + 32768u;
#pragma unroll
    for (uint32_t s = 0; s < 4; ++s) {
        uint32_t a[4][4];
#pragma unroll
        for (int mi = 0; mi < 4; ++mi)
            LDSM4(a[mi][0], a[mi][1], a[mi][2], a[mi][3],
                  aSt + pA + mi * 2048u + (((2u * s) ^ rxA) << 4));
        uint32_t b[2][4];
#pragma unroll
        for (int j = 0; j < 2; ++j)
            LDSM4(b[j][0], b[j][1], b[j][2], b[j][3],
                  wSt + pB + j * 2048u + (((2u * s) ^ rxB) << 4));
#pragma unroll
        for (int mi = 0; mi < 4; ++mi) {
            MMA(c[mi][0], a[mi], b[0][0], b[0][1]);
            MMA(c[mi][1], a[mi], b[0][2], b[0][3]);
            MMA(c[mi][2], a[mi], b[1][0], b[1][1]);
            MMA(c[mi][3], a[mi], b[1][2], b[1][3]);
        }
    }
}

// ---------------- prep ----------------
__global__ void k_prepW(const float* __restrict__ Wa,
                        const float* __restrict__ Wb,
                        const float* __restrict__ W1) {
    const int t = blockIdx.x * 256 + threadIdx.x;
    if (t < 27 * 64 * 32) {
        const int k = t / 2048, o = (t % 2048) / 32, i = t % 32;
        g_Wat[t] = totf32(Wa[k * 2048 + i * 64 + o]);
    }
    if (t < 27 * 64 * 64) {
        const int k = t / 4096, o = (t % 4096) / 64, i = t % 64;
        g_Wbt[t] = totf32(Wb[k * 4096 + i * 64 + o]);
    }
    if (t < 2048) {
        const int o = t / 32, i = t % 32;
        g_W1t[t] = totf32(W1[i * 64 + o]);
    }
}
__global__ void k_prepX(const float* __restrict__ x, long long n32) {
    for (long long i = blockIdx.x * 256LL + threadIdx.x; i < n32;
         i += (long long)gridDim.x * 256)
        g_xt[i] = totf32(x[i]);
}

static constexpr int STG = 40960;          // A 32KB + W 8KB
static constexpr int NEI = 27648;          // 256*27 ints
static constexpr int AB_SM = NEI + 2 * STG;   // 109568
static constexpr int S_SM  = STG;             // 40960

// lane-constant fragment descriptors
struct Frag {
    uint32_t pA, pB, rxA, rxB;
    int g, t, mb, nb;
};
__device__ __forceinline__ Frag mkfrag(int wid, int lid) {
    Frag f;
    const uint32_t r = lid & 7, h8 = (lid >> 3) & 1, kp = (uint32_t)lid >> 4;
    const uint32_t q = (uint32_t)lid >> 3;
    const int warpM = wid & 3, warpN = wid >> 2;
    f.pA  = (warpM * 64 + h8 * 8 + r) * 128u;
    f.rxA = kp ^ r;
    f.pB  = (warpN * 32 + (q >> 1) * 8 + r) * 128u;
    f.rxB = (q & 1) ^ r;
    f.g = lid >> 2; f.t = lid & 3;
    f.mb = warpM * 64; f.nb = warpN * 32;
    return f;
}

// ---------------- kS: shortcut GN_s(x @ W1) -> g_sc ----------------
__global__ void __launch_bounds__(256, 2) kS(
    const float* __restrict__ gsw, const float* __restrict__ gsb, int n)
{
    extern __shared__ char smem[];
    const uint32_t aSt = s2u(smem);
    const int tid = threadIdx.x, wid = tid >> 5, lid = tid & 31;
    const int tile = blockIdx.x;
    const int rows = min(256, n - tile * 256);
    const int seg = tid & 7, r0 = tid >> 3;
    const uint32_t sw16 = (uint32_t)(seg ^ (r0 & 7)) * 16u;

#pragma unroll
    for (int q = 0; q < 8; ++q) {
        const int row = r0 + 32 * q;
        const long long nd = (long long)tile * 256 + ((row < rows) ? row : 0);
        cpa16(aSt + (uint32_t)row * 128u + sw16, g_xt + nd * 32 + seg * 4);
    }
    cpa16(aSt + 32768u + (uint32_t)r0 * 128u + sw16, g_W1t + r0 * 32 + seg * 4);
    cpa16(aSt + 32768u + 4096u + (uint32_t)r0 * 128u + sw16,
          g_W1t + (r0 + 32) * 32 + seg * 4);
    CPA_COMMIT();

    float c[4][4][4];
#pragma unroll
    for (int mi = 0; mi < 4; ++mi)
#pragma unroll
        for (int nn = 0; nn < 4; ++nn)
#pragma unroll
            for (int j = 0; j < 4; ++j) c[mi][nn][j] = 0.f;

    CPA_WAIT0();
    __syncthreads();
    const Frag f = mkfrag(wid, lid);
    mma_stage(aSt, c, f.pA, f.pB, f.rxA, f.rxB);

#pragma unroll
    for (int mi = 0; mi < 4; ++mi)
#pragma unroll
        for (int h = 0; h < 2; ++h) {
            const int row = f.mb + mi * 16 + f.g + 8 * h;
#pragma unroll
            for (int nn = 0; nn < 4; ++nn) {
                const float v0 = c[mi][nn][2 * h], v1 = c[mi][nn][2 * h + 1];
                float s = v0 + v1;
                s += __shfl_xor_sync(0xffffffffu, s, 1);
                const float mu = s * 0.25f;
                const float d0 = v0 - mu, d1 = v1 - mu;
                float qv = d0 * d0 + d1 * d1;
                qv += __shfl_xor_sync(0xffffffffu, qv, 1);
                const float rs = rsqrtf(qv * 0.25f + 1e-5f);
                const int col = f.nb + nn * 8 + f.t * 2;
                if (row < rows) {
                    float2 o;
                    o.x = fmaf(d0 * rs, __ldg(gsw + col), __ldg(gsb + col));
                    o.y = fmaf(d1 * rs, __ldg(gsw + col + 1), __ldg(gsb + col + 1));
                    *(float2*)(g_sc + ((long long)tile * 256 + row) * 64 + col) = o;
                }
            }
        }
}

// ---------------- kA: 27 K=32 taps -> g_h ----------------
__global__ void __launch_bounds__(256, 2) kA(
    const int* __restrict__ neigh, const float* __restrict__ gw,
    const float* __restrict__ gb, int n)
{
    extern __shared__ char smem[];
    int* snei = (int*)smem;
    const uint32_t sb = s2u(smem) + (uint32_t)NEI;
    const int tid = threadIdx.x, wid = tid >> 5, lid = tid & 31;
    const int tile = blockIdx.x;
    const int rows = min(256, n - tile * 256);

    for (int i = tid; i < 256 * 27; i += 256) {
        int v = 0;
        if (i < rows * 27) v = neigh[(long long)tile * 256 * 27 + i];
        snei[i] = v;
    }
    __syncthreads();

    const int seg = tid & 7, r0 = tid >> 3;
    const uint32_t sw16 = (uint32_t)(seg ^ (r0 & 7)) * 16u;
    const uint32_t aDst = sb + (uint32_t)r0 * 128u + sw16;
    const uint32_t wDst = sb + 32768u + (uint32_t)r0 * 128u + sw16;
    const int* nrow = snei + r0 * 27;
    const float* wsrc = g_Wat + r0 * 32 + seg * 4;

    float c[4][4][4];
#pragma unroll
    for (int mi = 0; mi < 4; ++mi)
#pragma unroll
        for (int nn = 0; nn < 4; ++nn)
#pragma unroll
            for (int j = 0; j < 4; ++j) c[mi][nn][j] = 0.f;

    auto stage = [&](int k, uint32_t so) {
#pragma unroll
        for (int q = 0; q < 8; ++q) {
            const long long idx = nrow[q * 864 + k];
            cpa16(aDst + so + q * 4096u, g_xt + idx * 32 + seg * 4);
        }
        cpa16(wDst + so, wsrc + k * 2048);
        cpa16(wDst + so + 4096u, wsrc + k * 2048 + 1024);
        CPA_COMMIT();
    };

    const Frag f = mkfrag(wid, lid);
    stage(0, 0);
#pragma unroll 1
    for (int k = 0; k < 27; ++k) {
        const uint32_t so = (k & 1) ? (uint32_t)STG : 0u;
        CPA_WAIT0();
        __syncthreads();
        if (k + 1 < 27) stage(k + 1, so ^ (uint32_t)STG); else CPA_COMMIT();
        mma_stage(sb + so, c, f.pA, f.pB, f.rxA, f.rxB);
    }

#pragma unroll
    for (int mi = 0; mi < 4; ++mi)
#pragma unroll
        for (int h = 0; h < 2; ++h) {
            const int row = f.mb + mi * 16 + f.g + 8 * h;
#pragma unroll
            for (int nn = 0; nn < 4; ++nn) {
                const float v0 = c[mi][nn][2 * h], v1 = c[mi][nn][2 * h + 1];
                float s = v0 + v1;
                s += __shfl_xor_sync(0xffffffffu, s, 1);
                const float mu = s * 0.25f;
                const float d0 = v0 - mu, d1 = v1 - mu;
                float qv = d0 * d0 + d1 * d1;
                qv += __shfl_xor_sync(0xffffffffu, qv, 1);
                const float rs = rsqrtf(qv * 0.25f + 1e-5f);
                const int col = f.nb + nn * 8 + f.t * 2;
                if (row < rows) {
                    float2 o;
                    o.x = totf32(fmaxf(fmaf(d0 * rs, __ldg(gw + col),
                                            __ldg(gb + col)), 0.f));
                    o.y = totf32(fmaxf(fmaf(d1 * rs, __ldg(gw + col + 1),
                                            __ldg(gb + col + 1)), 0.f));
                    *(float2*)(g_h + ((long long)tile * 256 + row) * 64 + col) = o;
                }
            }
        }
}

// ---------------- kB: 54 K=32 half-taps -> out ----------------
__global__ void __launch_bounds__(256, 2) kB(
    const int* __restrict__ neigh,
    const float* __restrict__ gbw, const float* __restrict__ gbb,
    float* __restrict__ out, int n)
{
    extern __shared__ char smem[];
    int* snei = (int*)smem;
    const uint32_t sb = s2u(smem) + (uint32_t)NEI;
    const int tid = threadIdx.x, wid = tid >> 5, lid = tid & 31;
    const int tile = blockIdx.x;
    const int rows = min(256, n - tile * 256);

    for (int i = tid; i < 256 * 27; i += 256) {
        int v = 0;
        if (i < rows * 27) v = neigh[(long long)tile * 256 * 27 + i];
        snei[i] = v;
    }
    __syncthreads();

    const int seg = tid & 7, r0 = tid >> 3;
    const uint32_t sw16 = (uint32_t)(seg ^ (r0 & 7)) * 16u;
    const uint32_t aDst = sb + (uint32_t)r0 * 128u + sw16;
    const uint32_t wDst = sb + 32768u + (uint32_t)r0 * 128u + sw16;
    const int* nrow = snei + r0 * 27;
    const float* wsrc = g_Wbt + r0 * 64 + seg * 4;

    float c[4][4][4];
#pragma unroll
    for (int mi = 0; mi < 4; ++mi)
#pragma unroll
        for (int nn = 0; nn < 4; ++nn)
#pragma unroll
            for (int j = 0; j < 4; ++j) c[mi][nn][j] = 0.f;

    auto stage = [&](int k, int hf, uint32_t so) {
#pragma unroll
        for (int q = 0; q < 8; ++q) {
            const long long idx = nrow[q * 864 + k];
            cpa16(aDst + so + q * 4096u, g_h + idx * 64 + hf * 32 + seg * 4);
        }
        cpa16(wDst + so, wsrc + k * 4096 + hf * 32);
        cpa16(wDst + so + 4096u, wsrc + k * 4096 + hf * 32 + 2048);
        CPA_COMMIT();
    };

    const Frag f = mkfrag(wid, lid);
    stage(0, 0, 0u);
#pragma unroll 1
    for (int k = 0; k < 27; ++k) {
        // s = 2k (buf0): prefetch (k,1)->buf1, compute (k,0)
        CPA_WAIT0();
        __syncthreads();
        stage(k, 1, (uint32_t)STG);
        mma_stage(sb, c, f.pA, f.pB, f.rxA, f.rxB);
        // s = 2k+1 (buf1): prefetch (k+1,0)->buf0, compute (k,1)
        CPA_WAIT0();
        __syncthreads();
        if (k + 1 < 27) stage(k + 1, 0, 0u); else CPA_COMMIT();
        mma_stage(sb + (uint32_t)STG, c, f.pA, f.pB, f.rxA, f.rxB);
    }

#pragma unroll
    for (int mi = 0; mi < 4; ++mi)
#pragma unroll
        for (int h = 0; h < 2; ++h) {
            const int row = f.mb + mi * 16 + f.g + 8 * h;
#pragma unroll
            for (int nn = 0; nn < 4; ++nn) {
                const float v0 = c[mi][nn][2 * h], v1 = c[mi][nn][2 * h + 1];
                float s = v0 + v1;
                s += __shfl_xor_sync(0xffffffffu, s, 1);
                const float mub = s * 0.25f;
                const float d0 = v0 - mub, d1 = v1 - mub;
                float qv = d0 * d0 + d1 * d1;
                qv += __shfl_xor_sync(0xffffffffu, qv, 1);
                const float rb = rsqrtf(qv * 0.25f + 1e-5f);
                const int col = f.nb + nn * 8 + f.t * 2;
                if (row < rows) {
                    const long long base = ((long long)tile * 256 + row) * 64 + col;
                    const float2 sc = *(const float2*)(g_sc + base);
                    float2 o;
                    o.x = fmaxf(fmaf(d0 * rb, __ldg(gbw + col),
                                     __ldg(gbb + col)) + sc.x, 0.f);
                    o.y = fmaxf(fmaf(d1 * rb, __ldg(gbw + col + 1),
                                     __ldg(gbb + col + 1)) + sc.y, 0.f);
                    *(float2*)(out + base) = o;
                }
            }
        }
}

// ---------------------------------------------------------------------------
extern "C" void kernel_launch(void* const* d_in, const int* in_sizes, int n_in,
                              void* d_out, int out_size) {
    const float* data  = (const float*)d_in[0];
    const int*   neigh = (const int*)d_in[1];
    const float* Wa    = (const float*)d_in[2];
    const float* ga_w  = (const float*)d_in[3];
    const float* ga_b  = (const float*)d_in[4];
    const float* Wb    = (const float*)d_in[5];
    const float* gb_w  = (const float*)d_in[6];
    const float* gb_b  = (const float*)d_in[7];
    const float* W1    = (const float*)d_in[8];
    const float* gs_w  = (const float*)d_in[9];
    const float* gs_b  = (const float*)d_in[10];
    float* out = (float*)d_out;

    const int n = in_sizes[0] / 32;
    const int tiles = (n + 255) / 256;

    cudaFuncSetAttribute(kS, cudaFuncAttributeMaxDynamicSharedMemorySize, S_SM);
    cudaFuncSetAttribute(kA, cudaFuncAttributeMaxDynamicSharedMemorySize, AB_SM);
    cudaFuncSetAttribute(kB, cudaFuncAttributeMaxDynamicSharedMemorySize, AB_SM);

    k_prepW<<<(27 * 64 * 64 + 255) / 256, 256>>>(Wa, Wb, W1);
    k_prepX<<<2048, 256>>>(data, (long long)n * 32);
    kS<<<tiles, 256, S_SM>>>(gs_w, gs_b, n);
    kA<<<tiles, 256, AB_SM>>>(neigh, ga_w, ga_b, n);
    kB<<<tiles, 256, AB_SM>>>(neigh, gb_w, gb_b, out, n);
}